// round 10
// baseline (speedup 1.0000x reference)
#include <cuda_runtime.h>
#include <cstdint>

#define N_POI_C  100000
#define N_EDGE_C 50000
#define NNZ_MAX  3200000
#define EMB      128
#define SCAN_B   1024
#define NCHUNK   4

// ---------------- scratch: TWO independent CSR buffer sets (for stream overlap) ----
__device__ int   g_cnt0[N_EDGE_C];
__device__ int   g_rowptr0[N_EDGE_C + 1];
__device__ int   g_cursor0[N_EDGE_C];
__device__ int   g_bsum0[128];
__device__ int2  g_pack0[NNZ_MAX];

__device__ int   g_cnt1[N_POI_C];
__device__ int   g_rowptr1[N_POI_C + 1];
__device__ int   g_cursor1[N_POI_C];
__device__ int   g_bsum1[128];
__device__ int2  g_pack1[NNZ_MAX];

__device__ float g_S1[(size_t)N_EDGE_C * EMB];          // spmm(pte, poi_embs)
__device__ float g_Wc1[EMB * EMB];                      // W_poi  @ Wf[0:128]
__device__ float g_Wc2[EMB * EMB];                      // W_edge @ Wf[128:256]

template<int S> __device__ __forceinline__ int*  CNT()    { return S ? g_cnt1    : g_cnt0; }
template<int S> __device__ __forceinline__ int*  ROWPTR() { return S ? g_rowptr1 : g_rowptr0; }
template<int S> __device__ __forceinline__ int*  CURSOR() { return S ? g_cursor1 : g_cursor0; }
template<int S> __device__ __forceinline__ int*  BSUM()   { return S ? g_bsum1   : g_bsum0; }
template<int S> __device__ __forceinline__ int2* PACK()   { return S ? g_pack1   : g_pack0; }

// ---------------- tiny weight-fold GEMMs: Wc1/Wc2 (128x128 each) ----------------
__global__ void wc_kernel(const float* __restrict__ Wp,
                          const float* __restrict__ We,
                          const float* __restrict__ Wf) {
    __shared__ float srow[EMB];
    int i = blockIdx.x;            // output row
    int j = threadIdx.x;           // output col
    const float* W  = blockIdx.y ? We : Wp;
    const float* Bf = Wf + (blockIdx.y ? EMB * EMB : 0);
    srow[j] = W[i * EMB + j];
    __syncthreads();
    float acc = 0.f;
#pragma unroll 8
    for (int k = 0; k < EMB; ++k)
        acc = fmaf(srow[k], Bf[k * EMB + j], acc);
    (blockIdx.y ? g_Wc2 : g_Wc1)[i * EMB + j] = acc;
}

// ---------------- CSR build ----------------
template<int S>
__global__ void zero_kernel(int n) {
    int* cnt = CNT<S>();
    for (int i = blockIdx.x * blockDim.x + threadIdx.x; i < n;
         i += gridDim.x * blockDim.x)
        cnt[i] = 0;
}

template<int S>
__global__ void hist_kernel(const int* __restrict__ rows, int nnz) {
    int* cnt = CNT<S>();
    int stride = gridDim.x * blockDim.x;
    int tid = blockIdx.x * blockDim.x + threadIdx.x;
    int n4 = nnz >> 2;
    const int4* r4 = (const int4*)rows;
    for (int i = tid; i < n4; i += stride) {
        int4 r = __ldg(r4 + i);
        atomicAdd(&cnt[r.x], 1);
        atomicAdd(&cnt[r.y], 1);
        atomicAdd(&cnt[r.z], 1);
        atomicAdd(&cnt[r.w], 1);
    }
    for (int i = n4 * 4 + tid; i < nnz; i += stride)
        atomicAdd(&cnt[rows[i]], 1);
}

// --- scan pass 1: per-block (1024-elem) sums ---
template<int S>
__global__ __launch_bounds__(SCAN_B) void scan_pass1(int n) {
    __shared__ int ws[32];
    int tid = threadIdx.x, lane = tid & 31, wid = tid >> 5;
    int i = blockIdx.x * SCAN_B + tid;
    int s = (i < n) ? CNT<S>()[i] : 0;
#pragma unroll
    for (int d = 16; d > 0; d >>= 1) s += __shfl_down_sync(0xFFFFFFFFu, s, d);
    if (lane == 0) ws[wid] = s;
    __syncthreads();
    if (wid == 0) {
        int t = ws[lane];
#pragma unroll
        for (int d = 16; d > 0; d >>= 1) t += __shfl_down_sync(0xFFFFFFFFu, t, d);
        if (lane == 0) BSUM<S>()[blockIdx.x] = t;
    }
}

// --- scan pass 2 (fused into 3): each block computes its own prefix over bsum,
//     then scans its 1024 elements and writes rowptr/cursor ---
template<int S>
__global__ __launch_bounds__(SCAN_B) void scan_pass3(int n) {
    __shared__ int ws[32];
    __shared__ int s_boff;
    int tid = threadIdx.x, lane = tid & 31, wid = tid >> 5;
    // warp 0: prefix of block sums [0, blockIdx.x)
    if (wid == 0) {
        int acc = 0;
        for (int b = lane; b < (int)blockIdx.x; b += 32) acc += BSUM<S>()[b];
#pragma unroll
        for (int d = 16; d > 0; d >>= 1) acc += __shfl_down_sync(0xFFFFFFFFu, acc, d);
        if (lane == 0) s_boff = acc;
    }
    int i = blockIdx.x * SCAN_B + tid;
    int v = (i < n) ? CNT<S>()[i] : 0;
    int x = v;
#pragma unroll
    for (int d = 1; d < 32; d <<= 1) {
        int t = __shfl_up_sync(0xFFFFFFFFu, x, d);
        if (lane >= d) x += t;
    }
    if (lane == 31) ws[wid] = x;
    __syncthreads();
    if (wid == 0) {
        int w = ws[lane];
#pragma unroll
        for (int d = 1; d < 32; d <<= 1) {
            int t = __shfl_up_sync(0xFFFFFFFFu, w, d);
            if (lane >= d) w += t;
        }
        ws[lane] = w;
    }
    __syncthreads();
    int woff = wid ? ws[wid - 1] : 0;
    int excl = (x - v) + woff + s_boff;
    if (i < n) {
        ROWPTR<S>()[i] = excl;
        CURSOR<S>()[i] = excl;
        if (i == n - 1) ROWPTR<S>()[n] = excl + v;
    }
}

template<int S>
__global__ void scatter_kernel(const int* __restrict__ rows,
                               const int* __restrict__ cols,
                               const float* __restrict__ vals, int nnz) {
    int*  cur  = CURSOR<S>();
    int2* pack = PACK<S>();
    int stride = gridDim.x * blockDim.x;
    int tid = blockIdx.x * blockDim.x + threadIdx.x;
    int n4 = nnz >> 2;
    const int4*   r4 = (const int4*)rows;
    const int4*   c4 = (const int4*)cols;
    const float4* v4 = (const float4*)vals;
    for (int i = tid; i < n4; i += stride) {
        int4 r = __ldg(r4 + i);
        int4 c = __ldg(c4 + i);
        float4 v = __ldg(v4 + i);
        int p0 = atomicAdd(&cur[r.x], 1);
        int p1 = atomicAdd(&cur[r.y], 1);
        int p2 = atomicAdd(&cur[r.z], 1);
        int p3 = atomicAdd(&cur[r.w], 1);
        pack[p0] = make_int2(c.x, __float_as_int(v.x));
        pack[p1] = make_int2(c.y, __float_as_int(v.y));
        pack[p2] = make_int2(c.z, __float_as_int(v.z));
        pack[p3] = make_int2(c.w, __float_as_int(v.w));
    }
    for (int i = n4 * 4 + tid; i < nnz; i += stride) {
        int pos = atomicAdd(&cur[rows[i]], 1);
        pack[pos] = make_int2(cols[i], __float_as_int(vals[i]));
    }
}

// ---------------- CSR SpMM: one warp per output row, float4 per lane ----------------
// rows [base, end); out == nullptr -> write to g_S1
template<int S>
__global__ __launch_bounds__(128) void spmm_kernel(const float* __restrict__ dense,
                                                   float* __restrict__ out,
                                                   int base, int end) {
    int r = base + blockIdx.x * 4 + (threadIdx.x >> 5);
    if (r >= end) return;
    int lane = threadIdx.x & 31;
    const int*  rowptr = ROWPTR<S>();
    const int2* pack   = PACK<S>();
    int s = __ldg(&rowptr[r]);
    int e = __ldg(&rowptr[r + 1]);
    float* o = out ? out : (float*)g_S1;
    float4 acc = make_float4(0.f, 0.f, 0.f, 0.f);
    int j = s;
    for (; j + 4 <= e; j += 4) {
        int2 p0 = __ldg(&pack[j + 0]);
        int2 p1 = __ldg(&pack[j + 1]);
        int2 p2 = __ldg(&pack[j + 2]);
        int2 p3 = __ldg(&pack[j + 3]);
        float4 d0 = __ldg((const float4*)(dense + (size_t)p0.x * EMB) + lane);
        float4 d1 = __ldg((const float4*)(dense + (size_t)p1.x * EMB) + lane);
        float4 d2 = __ldg((const float4*)(dense + (size_t)p2.x * EMB) + lane);
        float4 d3 = __ldg((const float4*)(dense + (size_t)p3.x * EMB) + lane);
        float v0 = __int_as_float(p0.y), v1 = __int_as_float(p1.y);
        float v2 = __int_as_float(p2.y), v3 = __int_as_float(p3.y);
        acc.x = fmaf(v0, d0.x, acc.x); acc.y = fmaf(v0, d0.y, acc.y);
        acc.z = fmaf(v0, d0.z, acc.z); acc.w = fmaf(v0, d0.w, acc.w);
        acc.x = fmaf(v1, d1.x, acc.x); acc.y = fmaf(v1, d1.y, acc.y);
        acc.z = fmaf(v1, d1.z, acc.z); acc.w = fmaf(v1, d1.w, acc.w);
        acc.x = fmaf(v2, d2.x, acc.x); acc.y = fmaf(v2, d2.y, acc.y);
        acc.z = fmaf(v2, d2.z, acc.z); acc.w = fmaf(v2, d2.w, acc.w);
        acc.x = fmaf(v3, d3.x, acc.x); acc.y = fmaf(v3, d3.y, acc.y);
        acc.z = fmaf(v3, d3.z, acc.z); acc.w = fmaf(v3, d3.w, acc.w);
    }
    for (; j < e; ++j) {
        int2 p = __ldg(&pack[j]);
        float4 d = __ldg((const float4*)(dense + (size_t)p.x * EMB) + lane);
        float v = __int_as_float(p.y);
        acc.x = fmaf(v, d.x, acc.x); acc.y = fmaf(v, d.y, acc.y);
        acc.z = fmaf(v, d.z, acc.z); acc.w = fmaf(v, d.w, acc.w);
    }
    *(float4*)(o + (size_t)r * EMB + lane * 4) = acc;
}

// ---------------- split GEMM: MODE 0: F = E@Wc2 ; MODE 1: F += S1@Wc1 ----------------
// rows [base, end); 64-row tiles, 256 threads, 8x4 microtile, BK=32, K=128.
template<int MODE>
__global__ __launch_bounds__(256) void gemm_kernel(const float* __restrict__ Ain,
                                                   float* __restrict__ F,
                                                   int base, int end) {
    __shared__ __align__(16) float sA[32][68];
    __shared__ __align__(16) float sB[32][128];
    int tid = threadIdx.x;
    int tr = tid >> 5;
    int tc = tid & 31;
    int row0 = base + blockIdx.x * 64;
    const float* A = MODE ? (const float*)g_S1 : Ain;
    const float* B = MODE ? (const float*)g_Wc1 : (const float*)g_Wc2;

    float acc[8][4];
    if (MODE) {
#pragma unroll
        for (int i = 0; i < 8; ++i) {
            int r = row0 + tr * 8 + i;
            float4 c = (r < end)
                ? *(const float4*)(F + (size_t)r * EMB + tc * 4)
                : make_float4(0.f, 0.f, 0.f, 0.f);
            acc[i][0] = c.x; acc[i][1] = c.y; acc[i][2] = c.z; acc[i][3] = c.w;
        }
    } else {
#pragma unroll
        for (int i = 0; i < 8; ++i)
#pragma unroll
            for (int c = 0; c < 4; ++c) acc[i][c] = 0.f;
    }

#pragma unroll 1
    for (int chunk = 0; chunk < 4; ++chunk) {
        int k0 = chunk * 32;
#pragma unroll
        for (int q = 0; q < 2; ++q) {
            int lin = tid * 2 + q;
            int m   = lin >> 3;
            int kk  = (lin & 7) << 2;
            float4 a4 = make_float4(0.f, 0.f, 0.f, 0.f);
            if (row0 + m < end)
                a4 = *(const float4*)(A + (size_t)(row0 + m) * EMB + k0 + kk);
            sA[kk + 0][m] = a4.x; sA[kk + 1][m] = a4.y;
            sA[kk + 2][m] = a4.z; sA[kk + 3][m] = a4.w;
        }
#pragma unroll
        for (int q = 0; q < 4; ++q) {
            int lin = tid * 4 + q;
            int k = lin >> 5, c4 = lin & 31;
            *(float4*)(&sB[k][c4 * 4]) =
                *(const float4*)(B + (size_t)(k0 + k) * EMB + c4 * 4);
        }
        __syncthreads();
#pragma unroll
        for (int k = 0; k < 32; ++k) {
            float4 b  = *(const float4*)(&sB[k][tc * 4]);
            float4 a0 = *(const float4*)(&sA[k][tr * 8]);
            float4 a1 = *(const float4*)(&sA[k][tr * 8 + 4]);
            float av[8] = {a0.x, a0.y, a0.z, a0.w, a1.x, a1.y, a1.z, a1.w};
#pragma unroll
            for (int i = 0; i < 8; ++i) {
                acc[i][0] = fmaf(av[i], b.x, acc[i][0]);
                acc[i][1] = fmaf(av[i], b.y, acc[i][1]);
                acc[i][2] = fmaf(av[i], b.z, acc[i][2]);
                acc[i][3] = fmaf(av[i], b.w, acc[i][3]);
            }
        }
        __syncthreads();
    }
#pragma unroll
    for (int i = 0; i < 8; ++i) {
        int r = row0 + tr * 8 + i;
        if (r < end)
            *(float4*)(F + (size_t)r * EMB + tc * 4) =
                make_float4(acc[i][0], acc[i][1], acc[i][2], acc[i][3]);
    }
}

// ---------------- launch ----------------
template<int S>
static inline void build_csr(const int* rows, const int* cols, const float* vals,
                             int nnz, int nrows, cudaStream_t st) {
    int nblocks = (nrows + SCAN_B - 1) / SCAN_B;
    zero_kernel<S><<<256, 256, 0, st>>>(nrows);
    hist_kernel<S><<<1024, 256, 0, st>>>(rows, nnz);
    scan_pass1<S><<<nblocks, SCAN_B, 0, st>>>(nrows);
    scan_pass3<S><<<nblocks, SCAN_B, 0, st>>>(nrows);
    scatter_kernel<S><<<1024, 256, 0, st>>>(rows, cols, vals, nnz);
}

static cudaStream_t g_s2  = nullptr;   // CSR2 build
static cudaStream_t g_s3  = nullptr;   // gemmB + gemmA chunks
static cudaEvent_t  g_evF  = nullptr;  // fork
static cudaEvent_t  g_evJ  = nullptr;  // CSR2 done
static cudaEvent_t  g_evWc = nullptr;  // wc done
static cudaEvent_t  g_evA  = nullptr;  // all gemmA chunks done
static cudaEvent_t  g_evS[NCHUNK] = {};

extern "C" void kernel_launch(void* const* d_in, const int* in_sizes, int n_in,
                              void* d_out, int out_size) {
    const float* poi  = (const float*)d_in[0];
    const float* edge = (const float*)d_in[1];
    const int*   pr   = (const int*)d_in[2];
    const int*   pc   = (const int*)d_in[3];
    const float* pv   = (const float*)d_in[4];
    const int*   er   = (const int*)d_in[5];
    const int*   ec   = (const int*)d_in[6];
    const float* evv  = (const float*)d_in[7];
    const float* Wp   = (const float*)d_in[8];
    const float* We   = (const float*)d_in[9];
    const float* Wf   = (const float*)d_in[10];
    int nnz1 = in_sizes[2];
    int nnz2 = in_sizes[5];

    float* prop = (float*)d_out;                       // [100000, 128]
    float* F    = prop + (size_t)N_POI_C * EMB;        // [50000, 128]

    if (!g_s2) {
        cudaStreamCreateWithFlags(&g_s2, cudaStreamNonBlocking);
        cudaStreamCreateWithFlags(&g_s3, cudaStreamNonBlocking);
        cudaEventCreateWithFlags(&g_evF,  cudaEventDisableTiming);
        cudaEventCreateWithFlags(&g_evJ,  cudaEventDisableTiming);
        cudaEventCreateWithFlags(&g_evWc, cudaEventDisableTiming);
        cudaEventCreateWithFlags(&g_evA,  cudaEventDisableTiming);
        for (int c = 0; c < NCHUNK; ++c)
            cudaEventCreateWithFlags(&g_evS[c], cudaEventDisableTiming);
    }

    // ---- fork ----
    cudaEventRecord(g_evF, 0);

    // side stream A: CSR build for etp (set 1)
    cudaStreamWaitEvent(g_s2, g_evF, 0);
    build_csr<1>(er, ec, evv, nnz2, N_POI_C, g_s2);
    cudaEventRecord(g_evJ, g_s2);

    // main: fold weights first (gemmB needs Wc2)
    wc_kernel<<<dim3(128, 2), 128>>>(Wp, We, Wf);
    cudaEventRecord(g_evWc, 0);

    // side stream B: F = edge @ Wc2 (independent of SpMM1)
    cudaStreamWaitEvent(g_s3, g_evWc, 0);
    gemm_kernel<0><<<(N_EDGE_C + 63) / 64, 256, 0, g_s3>>>(edge, F, 0, N_EDGE_C);

    // main: CSR for pte (set 0)
    build_csr<0>(pr, pc, pv, nnz1, N_EDGE_C, 0);

    // main: SpMM1 in NCHUNK row-chunks; gemmA chunk follows each on g_s3
    const int CH = N_EDGE_C / NCHUNK;   // 12500
    for (int c = 0; c < NCHUNK; ++c) {
        int b = c * CH;
        int e = (c == NCHUNK - 1) ? N_EDGE_C : b + CH;
        spmm_kernel<0><<<(e - b + 3) / 4, 128>>>(poi, nullptr, b, e);
        cudaEventRecord(g_evS[c], 0);
        cudaStreamWaitEvent(g_s3, g_evS[c], 0);
        gemm_kernel<1><<<(e - b + 63) / 64, 256, 0, g_s3>>>(nullptr, F, b, e);
    }
    cudaEventRecord(g_evA, g_s3);

    // join gemmA + CSR2, then SpMM2: prop = etp @ F
    cudaStreamWaitEvent(0, g_evA, 0);
    cudaStreamWaitEvent(0, g_evJ, 0);
    spmm_kernel<1><<<(N_POI_C + 3) / 4, 128>>>(F, prop, 0, N_POI_C);
}

// round 11
// speedup vs baseline: 1.0940x; 1.0940x over previous
#include <cuda_runtime.h>
#include <cstdint>

#define N_POI_C  100000
#define N_EDGE_C 50000
#define NNZ_MAX  3200000
#define EMB      128
#define SCAN_B   1024

// ---------------- scratch: TWO independent CSR buffer sets (for stream overlap) ----
__device__ int   g_cnt0[N_EDGE_C];
__device__ int   g_rowptr0[N_EDGE_C + 1];
__device__ int   g_cursor0[N_EDGE_C];
__device__ int   g_bsum0[128];
__device__ int2  g_pack0[NNZ_MAX];

__device__ int   g_cnt1[N_POI_C];
__device__ int   g_rowptr1[N_POI_C + 1];
__device__ int   g_cursor1[N_POI_C];
__device__ int   g_bsum1[128];
__device__ int2  g_pack1[NNZ_MAX];

__device__ float g_S1[(size_t)N_EDGE_C * EMB];          // spmm(pte, poi_embs)
__device__ float g_Wc1[EMB * EMB];                      // W_poi  @ Wf[0:128]
__device__ float g_Wc2[EMB * EMB];                      // W_edge @ Wf[128:256]

template<int S> __device__ __forceinline__ int*  CNT()    { return S ? g_cnt1    : g_cnt0; }
template<int S> __device__ __forceinline__ int*  ROWPTR() { return S ? g_rowptr1 : g_rowptr0; }
template<int S> __device__ __forceinline__ int*  CURSOR() { return S ? g_cursor1 : g_cursor0; }
template<int S> __device__ __forceinline__ int*  BSUM()   { return S ? g_bsum1   : g_bsum0; }
template<int S> __device__ __forceinline__ int2* PACK()   { return S ? g_pack1   : g_pack0; }

// ---------------- tiny weight-fold GEMMs: Wc1/Wc2 (128x128 each) ----------------
__global__ void wc_kernel(const float* __restrict__ Wp,
                          const float* __restrict__ We,
                          const float* __restrict__ Wf) {
    __shared__ float srow[EMB];
    int i = blockIdx.x;            // output row
    int j = threadIdx.x;           // output col
    const float* W  = blockIdx.y ? We : Wp;
    const float* Bf = Wf + (blockIdx.y ? EMB * EMB : 0);
    srow[j] = W[i * EMB + j];
    __syncthreads();
    float acc = 0.f;
#pragma unroll 8
    for (int k = 0; k < EMB; ++k)
        acc = fmaf(srow[k], Bf[k * EMB + j], acc);
    (blockIdx.y ? g_Wc2 : g_Wc1)[i * EMB + j] = acc;
}

// ---------------- CSR build ----------------
template<int S>
__global__ void zero_kernel(int n) {
    int* cnt = CNT<S>();
    for (int i = blockIdx.x * blockDim.x + threadIdx.x; i < n;
         i += gridDim.x * blockDim.x)
        cnt[i] = 0;
}

template<int S>
__global__ void hist_kernel(const int* __restrict__ rows, int nnz) {
    int* cnt = CNT<S>();
    int stride = gridDim.x * blockDim.x;
    int tid = blockIdx.x * blockDim.x + threadIdx.x;
    int n4 = nnz >> 2;
    const int4* r4 = (const int4*)rows;
    for (int i = tid; i < n4; i += stride) {
        int4 r = __ldg(r4 + i);
        atomicAdd(&cnt[r.x], 1);
        atomicAdd(&cnt[r.y], 1);
        atomicAdd(&cnt[r.z], 1);
        atomicAdd(&cnt[r.w], 1);
    }
    for (int i = n4 * 4 + tid; i < nnz; i += stride)
        atomicAdd(&cnt[rows[i]], 1);
}

// --- scan pass 1: per-block (1024-elem) sums ---
template<int S>
__global__ __launch_bounds__(SCAN_B) void scan_pass1(int n) {
    __shared__ int ws[32];
    int tid = threadIdx.x, lane = tid & 31, wid = tid >> 5;
    int i = blockIdx.x * SCAN_B + tid;
    int s = (i < n) ? CNT<S>()[i] : 0;
#pragma unroll
    for (int d = 16; d > 0; d >>= 1) s += __shfl_down_sync(0xFFFFFFFFu, s, d);
    if (lane == 0) ws[wid] = s;
    __syncthreads();
    if (wid == 0) {
        int t = ws[lane];
#pragma unroll
        for (int d = 16; d > 0; d >>= 1) t += __shfl_down_sync(0xFFFFFFFFu, t, d);
        if (lane == 0) BSUM<S>()[blockIdx.x] = t;
    }
}

// --- scan pass 2 (fused): each block computes its own prefix over bsum,
//     then scans its 1024 elements and writes rowptr/cursor ---
template<int S>
__global__ __launch_bounds__(SCAN_B) void scan_pass3(int n) {
    __shared__ int ws[32];
    __shared__ int s_boff;
    int tid = threadIdx.x, lane = tid & 31, wid = tid >> 5;
    if (wid == 0) {
        int acc = 0;
        for (int b = lane; b < (int)blockIdx.x; b += 32) acc += BSUM<S>()[b];
#pragma unroll
        for (int d = 16; d > 0; d >>= 1) acc += __shfl_down_sync(0xFFFFFFFFu, acc, d);
        if (lane == 0) s_boff = acc;
    }
    int i = blockIdx.x * SCAN_B + tid;
    int v = (i < n) ? CNT<S>()[i] : 0;
    int x = v;
#pragma unroll
    for (int d = 1; d < 32; d <<= 1) {
        int t = __shfl_up_sync(0xFFFFFFFFu, x, d);
        if (lane >= d) x += t;
    }
    if (lane == 31) ws[wid] = x;
    __syncthreads();
    if (wid == 0) {
        int w = ws[lane];
#pragma unroll
        for (int d = 1; d < 32; d <<= 1) {
            int t = __shfl_up_sync(0xFFFFFFFFu, w, d);
            if (lane >= d) w += t;
        }
        ws[lane] = w;
    }
    __syncthreads();
    int woff = wid ? ws[wid - 1] : 0;
    int excl = (x - v) + woff + s_boff;
    if (i < n) {
        ROWPTR<S>()[i] = excl;
        CURSOR<S>()[i] = excl;
        if (i == n - 1) ROWPTR<S>()[n] = excl + v;
    }
}

template<int S>
__global__ void scatter_kernel(const int* __restrict__ rows,
                               const int* __restrict__ cols,
                               const float* __restrict__ vals, int nnz) {
    int*  cur  = CURSOR<S>();
    int2* pack = PACK<S>();
    int stride = gridDim.x * blockDim.x;
    int tid = blockIdx.x * blockDim.x + threadIdx.x;
    int n4 = nnz >> 2;
    const int4*   r4 = (const int4*)rows;
    const int4*   c4 = (const int4*)cols;
    const float4* v4 = (const float4*)vals;
    for (int i = tid; i < n4; i += stride) {
        int4 r = __ldg(r4 + i);
        int4 c = __ldg(c4 + i);
        float4 v = __ldg(v4 + i);
        int p0 = atomicAdd(&cur[r.x], 1);
        int p1 = atomicAdd(&cur[r.y], 1);
        int p2 = atomicAdd(&cur[r.z], 1);
        int p3 = atomicAdd(&cur[r.w], 1);
        pack[p0] = make_int2(c.x, __float_as_int(v.x));
        pack[p1] = make_int2(c.y, __float_as_int(v.y));
        pack[p2] = make_int2(c.z, __float_as_int(v.z));
        pack[p3] = make_int2(c.w, __float_as_int(v.w));
    }
    for (int i = n4 * 4 + tid; i < nnz; i += stride) {
        int pos = atomicAdd(&cur[rows[i]], 1);
        pack[pos] = make_int2(cols[i], __float_as_int(vals[i]));
    }
}

// ---------------- CSR SpMM: one warp per output row, float4 per lane ----------------
// out == nullptr -> write to g_S1
template<int S>
__global__ __launch_bounds__(128) void spmm_kernel(const float* __restrict__ dense,
                                                   float* __restrict__ out,
                                                   int nrows) {
    int r = blockIdx.x * 4 + (threadIdx.x >> 5);
    if (r >= nrows) return;
    int lane = threadIdx.x & 31;
    const int*  rowptr = ROWPTR<S>();
    const int2* pack   = PACK<S>();
    int s = __ldg(&rowptr[r]);
    int e = __ldg(&rowptr[r + 1]);
    float* o = out ? out : (float*)g_S1;
    float4 acc = make_float4(0.f, 0.f, 0.f, 0.f);
    int j = s;
    for (; j + 4 <= e; j += 4) {
        int2 p0 = __ldg(&pack[j + 0]);
        int2 p1 = __ldg(&pack[j + 1]);
        int2 p2 = __ldg(&pack[j + 2]);
        int2 p3 = __ldg(&pack[j + 3]);
        float4 d0 = __ldg((const float4*)(dense + (size_t)p0.x * EMB) + lane);
        float4 d1 = __ldg((const float4*)(dense + (size_t)p1.x * EMB) + lane);
        float4 d2 = __ldg((const float4*)(dense + (size_t)p2.x * EMB) + lane);
        float4 d3 = __ldg((const float4*)(dense + (size_t)p3.x * EMB) + lane);
        float v0 = __int_as_float(p0.y), v1 = __int_as_float(p1.y);
        float v2 = __int_as_float(p2.y), v3 = __int_as_float(p3.y);
        acc.x = fmaf(v0, d0.x, acc.x); acc.y = fmaf(v0, d0.y, acc.y);
        acc.z = fmaf(v0, d0.z, acc.z); acc.w = fmaf(v0, d0.w, acc.w);
        acc.x = fmaf(v1, d1.x, acc.x); acc.y = fmaf(v1, d1.y, acc.y);
        acc.z = fmaf(v1, d1.z, acc.z); acc.w = fmaf(v1, d1.w, acc.w);
        acc.x = fmaf(v2, d2.x, acc.x); acc.y = fmaf(v2, d2.y, acc.y);
        acc.z = fmaf(v2, d2.z, acc.z); acc.w = fmaf(v2, d2.w, acc.w);
        acc.x = fmaf(v3, d3.x, acc.x); acc.y = fmaf(v3, d3.y, acc.y);
        acc.z = fmaf(v3, d3.z, acc.z); acc.w = fmaf(v3, d3.w, acc.w);
    }
    for (; j < e; ++j) {
        int2 p = __ldg(&pack[j]);
        float4 d = __ldg((const float4*)(dense + (size_t)p.x * EMB) + lane);
        float v = __int_as_float(p.y);
        acc.x = fmaf(v, d.x, acc.x); acc.y = fmaf(v, d.y, acc.y);
        acc.z = fmaf(v, d.z, acc.z); acc.w = fmaf(v, d.w, acc.w);
    }
    *(float4*)(o + (size_t)r * EMB + lane * 4) = acc;
}

// ---------------- split GEMM: MODE 0: F = E@Wc2 ; MODE 1: F += S1@Wc1 ----------------
// 64-row tiles, 256 threads, 8x4 microtile per thread, BK=32, K=128 (4 chunks).
template<int MODE>
__global__ __launch_bounds__(256) void gemm_kernel(const float* __restrict__ Ain,
                                                   float* __restrict__ F,
                                                   int nrows) {
    __shared__ __align__(16) float sA[32][68];
    __shared__ __align__(16) float sB[32][128];
    int tid = threadIdx.x;
    int tr = tid >> 5;
    int tc = tid & 31;
    int row0 = blockIdx.x * 64;
    const float* A = MODE ? (const float*)g_S1 : Ain;
    const float* B = MODE ? (const float*)g_Wc1 : (const float*)g_Wc2;

    float acc[8][4];
    if (MODE) {
#pragma unroll
        for (int i = 0; i < 8; ++i) {
            int r = row0 + tr * 8 + i;
            float4 c = (r < nrows)
                ? *(const float4*)(F + (size_t)r * EMB + tc * 4)
                : make_float4(0.f, 0.f, 0.f, 0.f);
            acc[i][0] = c.x; acc[i][1] = c.y; acc[i][2] = c.z; acc[i][3] = c.w;
        }
    } else {
#pragma unroll
        for (int i = 0; i < 8; ++i)
#pragma unroll
            for (int c = 0; c < 4; ++c) acc[i][c] = 0.f;
    }

#pragma unroll 1
    for (int chunk = 0; chunk < 4; ++chunk) {
        int k0 = chunk * 32;
#pragma unroll
        for (int q = 0; q < 2; ++q) {
            int lin = tid * 2 + q;
            int m   = lin >> 3;
            int kk  = (lin & 7) << 2;
            float4 a4 = make_float4(0.f, 0.f, 0.f, 0.f);
            if (row0 + m < nrows)
                a4 = *(const float4*)(A + (size_t)(row0 + m) * EMB + k0 + kk);
            sA[kk + 0][m] = a4.x; sA[kk + 1][m] = a4.y;
            sA[kk + 2][m] = a4.z; sA[kk + 3][m] = a4.w;
        }
#pragma unroll
        for (int q = 0; q < 4; ++q) {
            int lin = tid * 4 + q;
            int k = lin >> 5, c4 = lin & 31;
            *(float4*)(&sB[k][c4 * 4]) =
                *(const float4*)(B + (size_t)(k0 + k) * EMB + c4 * 4);
        }
        __syncthreads();
#pragma unroll
        for (int k = 0; k < 32; ++k) {
            float4 b  = *(const float4*)(&sB[k][tc * 4]);
            float4 a0 = *(const float4*)(&sA[k][tr * 8]);
            float4 a1 = *(const float4*)(&sA[k][tr * 8 + 4]);
            float av[8] = {a0.x, a0.y, a0.z, a0.w, a1.x, a1.y, a1.z, a1.w};
#pragma unroll
            for (int i = 0; i < 8; ++i) {
                acc[i][0] = fmaf(av[i], b.x, acc[i][0]);
                acc[i][1] = fmaf(av[i], b.y, acc[i][1]);
                acc[i][2] = fmaf(av[i], b.z, acc[i][2]);
                acc[i][3] = fmaf(av[i], b.w, acc[i][3]);
            }
        }
        __syncthreads();
    }
#pragma unroll
    for (int i = 0; i < 8; ++i) {
        int r = row0 + tr * 8 + i;
        if (r < nrows)
            *(float4*)(F + (size_t)r * EMB + tc * 4) =
                make_float4(acc[i][0], acc[i][1], acc[i][2], acc[i][3]);
    }
}

// ---------------- launch ----------------
template<int S>
static inline void build_csr(const int* rows, const int* cols, const float* vals,
                             int nnz, int nrows, cudaStream_t st) {
    int nblocks = (nrows + SCAN_B - 1) / SCAN_B;
    zero_kernel<S><<<256, 256, 0, st>>>(nrows);
    hist_kernel<S><<<1024, 256, 0, st>>>(rows, nnz);
    scan_pass1<S><<<nblocks, SCAN_B, 0, st>>>(nrows);
    scan_pass3<S><<<nblocks, SCAN_B, 0, st>>>(nrows);
    scatter_kernel<S><<<1024, 256, 0, st>>>(rows, cols, vals, nnz);
}

static cudaStream_t g_s2  = nullptr;   // CSR2 build
static cudaStream_t g_s3  = nullptr;   // wc + gemmB
static cudaEvent_t  g_evF  = nullptr;  // fork
static cudaEvent_t  g_evJ  = nullptr;  // CSR2 done
static cudaEvent_t  g_evB  = nullptr;  // wc+gemmB done

extern "C" void kernel_launch(void* const* d_in, const int* in_sizes, int n_in,
                              void* d_out, int out_size) {
    const float* poi  = (const float*)d_in[0];
    const float* edge = (const float*)d_in[1];
    const int*   pr   = (const int*)d_in[2];
    const int*   pc   = (const int*)d_in[3];
    const float* pv   = (const float*)d_in[4];
    const int*   er   = (const int*)d_in[5];
    const int*   ec   = (const int*)d_in[6];
    const float* evv  = (const float*)d_in[7];
    const float* Wp   = (const float*)d_in[8];
    const float* We   = (const float*)d_in[9];
    const float* Wf   = (const float*)d_in[10];
    int nnz1 = in_sizes[2];
    int nnz2 = in_sizes[5];

    float* prop = (float*)d_out;                       // [100000, 128]
    float* F    = prop + (size_t)N_POI_C * EMB;        // [50000, 128]

    if (!g_s2) {
        cudaStreamCreateWithFlags(&g_s2, cudaStreamNonBlocking);
        cudaStreamCreateWithFlags(&g_s3, cudaStreamNonBlocking);
        cudaEventCreateWithFlags(&g_evF, cudaEventDisableTiming);
        cudaEventCreateWithFlags(&g_evJ, cudaEventDisableTiming);
        cudaEventCreateWithFlags(&g_evB, cudaEventDisableTiming);
    }

    // ---- fork ----
    cudaEventRecord(g_evF, 0);

    // side stream A: CSR build for etp (set 1)
    cudaStreamWaitEvent(g_s2, g_evF, 0);
    build_csr<1>(er, ec, evv, nnz2, N_POI_C, g_s2);
    cudaEventRecord(g_evJ, g_s2);

    // side stream B: weight fold, then F = edge @ Wc2 (both off the critical path)
    cudaStreamWaitEvent(g_s3, g_evF, 0);
    wc_kernel<<<dim3(128, 2), 128, 0, g_s3>>>(Wp, We, Wf);
    gemm_kernel<0><<<(N_EDGE_C + 63) / 64, 256, 0, g_s3>>>(edge, F, N_EDGE_C);
    cudaEventRecord(g_evB, g_s3);

    // main (critical path): CSR for pte (set 0), SpMM1 -> S1
    build_csr<0>(pr, pc, pv, nnz1, N_EDGE_C, 0);
    spmm_kernel<0><<<(N_EDGE_C + 3) / 4, 128>>>(poi, nullptr, N_EDGE_C);

    // main: F += S1 @ Wc1 (needs wc + gemmB done; evB also orders Wc1 writes)
    cudaStreamWaitEvent(0, g_evB, 0);
    gemm_kernel<1><<<(N_EDGE_C + 63) / 64, 256>>>(nullptr, F, N_EDGE_C);

    // join CSR2, then SpMM2: prop = etp @ F
    cudaStreamWaitEvent(0, g_evJ, 0);
    spmm_kernel<1><<<(N_POI_C + 3) / 4, 128>>>(F, prop, N_POI_C);
}